// round 3
// baseline (speedup 1.0000x reference)
#include <cuda_runtime.h>
#include <cuda_bf16.h>

// ---------------- problem constants ----------------
#define BB     16
#define CCH    256
#define HH     56
#define WWID   56
#define NN     3136          // 56*56
#define NHEADS 4
#define DK     16
#define DU     4
#define DVV    64
#define RR     15
// conv pad = 7

typedef unsigned long long ull;

// ---------------- scratch (device globals; no allocations allowed) ----------------
__device__ float g_q[BB * 64 * NN];    // [b][h*16+k][n]   (BN applied)
__device__ float g_k[BB * 64 * NN];    // [b][u*16+k][n]   (softmaxed in place)
__device__ float g_v[BB * 256 * NN];   // [b][u*64+v][n]   (BN applied)
__device__ float g_Lc[BB * DK * DVV];  // [b][k][v]

// ---------------- f32x2 helpers (sm_103a packed fp32 pipe) ----------------
__device__ __forceinline__ void ffma2(ull &d, ull a, ull b) {
    asm volatile("fma.rn.f32x2 %0, %1, %2, %0;" : "+l"(d) : "l"(a), "l"(b));
}
__device__ __forceinline__ void fadd2(ull &d, ull a) {
    asm volatile("add.rn.f32x2 %0, %0, %1;" : "+l"(d) : "l"(a));
}
__device__ __forceinline__ ull pack2(float x) {
    ull r; asm("mov.b64 %0, {%1, %1};" : "=l"(r) : "f"(x)); return r;
}
__device__ __forceinline__ ull fpack(float lo, float hi) {
    ull r; asm("mov.b64 %0, {%1, %2};" : "=l"(r) : "f"(lo), "f"(hi)); return r;
}
__device__ __forceinline__ void funpack(ull v, float &lo, float &hi) {
    asm("mov.b64 {%0, %1}, %2;" : "=f"(lo), "=f"(hi) : "l"(v));
}

// ---------------- kernel 0: zero Lc accumulator ----------------
__global__ void zero_lc_kernel() {
    int i = blockIdx.x * blockDim.x + threadIdx.x;
    if (i < BB * DK * DVV) g_Lc[i] = 0.f;
}

// ---------------- kernel 1: fused 1x1-conv projections + BatchNorm ----------------
// out[b, d, n] = sum_c x[b,c,n] * W[c,d], then BN (q and v only).
// grid (25 n-blocks of 128, 6 d-blocks of 64, 16 b), 256 threads.
__global__ void __launch_bounds__(256) proj_kernel(
    const float* __restrict__ x,
    const float* __restrict__ Wq, const float* __restrict__ Wk, const float* __restrict__ Wv,
    const float* __restrict__ gq, const float* __restrict__ bq,
    const float* __restrict__ mq, const float* __restrict__ vq,
    const float* __restrict__ gv, const float* __restrict__ bv,
    const float* __restrict__ mv, const float* __restrict__ vv)
{
    __shared__ float xs[32 * 128];
    __shared__ float Ws[32 * 64];

    const int b  = blockIdx.z;
    const int db = blockIdx.y;
    const int n0 = blockIdx.x * 128;
    const int t  = threadIdx.x;
    const int tx = t & 15;        // n-pair group
    const int ty = t >> 4;        // d group (4 channels each)

    const float* Wsrc; int dstride, dcol0;
    if (db == 0)      { Wsrc = Wq; dstride = 64;  dcol0 = 0; }
    else if (db == 1) { Wsrc = Wk; dstride = 64;  dcol0 = 0; }
    else              { Wsrc = Wv; dstride = 256; dcol0 = (db - 2) * 64; }

    ull acc[16];
#pragma unroll
    for (int i = 0; i < 16; i++) acc[i] = 0ull;

    for (int c0 = 0; c0 < CCH; c0 += 32) {
        __syncthreads();
        for (int s = t; s < 32 * 128; s += 256) {
            int cc = s >> 7, nn = s & 127;
            int g = n0 + nn;
            xs[s] = (g < NN) ? x[(size_t)(b * CCH + c0 + cc) * NN + g] : 0.f;
        }
        for (int s = t; s < 32 * 64; s += 256) {
            int cc = s >> 6, dd = s & 63;
            Ws[s] = Wsrc[(size_t)(c0 + cc) * dstride + dcol0 + dd];
        }
        __syncthreads();

#pragma unroll 8
        for (int ccl = 0; ccl < 32; ccl++) {
            ull xv[4];
#pragma unroll
            for (int j = 0; j < 4; j++)
                xv[j] = *(const ull*)&xs[ccl * 128 + ((tx + 16 * j) << 1)];
#pragma unroll
            for (int i = 0; i < 4; i++) {
                ull w2 = pack2(Ws[ccl * 64 + ty * 4 + i]);
#pragma unroll
                for (int j = 0; j < 4; j++) ffma2(acc[i * 4 + j], xv[j], w2);
            }
        }
    }

    // epilogue: BN + store
    float* dst;
    if (db == 0)      dst = g_q + (size_t)b * 64 * NN;
    else if (db == 1) dst = g_k + (size_t)b * 64 * NN;
    else              dst = g_v + ((size_t)b * 256 + dcol0) * NN;

    float sc[4], sh[4];
#pragma unroll
    for (int i = 0; i < 4; i++) {
        int d = ty * 4 + i;
        if (db == 0) {
            float inv = gq[d] * rsqrtf(vq[d] + 1e-5f);
            sc[i] = inv; sh[i] = bq[d] - mq[d] * inv;
        } else if (db == 1) {
            sc[i] = 1.f; sh[i] = 0.f;
        } else {
            int uvi = dcol0 + d;
            float inv = gv[uvi] * rsqrtf(vv[uvi] + 1e-5f);
            sc[i] = inv; sh[i] = bv[uvi] - mv[uvi] * inv;
        }
    }
#pragma unroll
    for (int i = 0; i < 4; i++) {
#pragma unroll
        for (int j = 0; j < 4; j++) {
            int n = n0 + ((tx + 16 * j) << 1);
            if (n < NN) {
                float lo, hi; funpack(acc[i * 4 + j], lo, hi);
                float* p = dst + (size_t)(ty * 4 + i) * NN + n;
                p[0] = lo * sc[i] + sh[i];
                p[1] = hi * sc[i] + sh[i];
            }
        }
    }
}

// ---------------- kernel 2: softmax over positions, in place on g_k ----------------
__global__ void __launch_bounds__(256) softmax_kernel() {
    const int row = blockIdx.x;                 // b*64 + u*16 + k
    float* base = g_k + (size_t)row * NN;
    const int t = threadIdx.x;
    __shared__ float red[8];

    float m = -3e38f;
    for (int i = t; i < NN; i += 256) m = fmaxf(m, base[i]);
#pragma unroll
    for (int o = 16; o; o >>= 1) m = fmaxf(m, __shfl_xor_sync(0xffffffffu, m, o));
    if ((t & 31) == 0) red[t >> 5] = m;
    __syncthreads();
    float mx = red[0];
#pragma unroll
    for (int w = 1; w < 8; w++) mx = fmaxf(mx, red[w]);
    __syncthreads();

    float s = 0.f;
    for (int i = t; i < NN; i += 256) {
        float e = expf(base[i] - mx);
        base[i] = e;
        s += e;
    }
#pragma unroll
    for (int o = 16; o; o >>= 1) s += __shfl_xor_sync(0xffffffffu, s, o);
    if ((t & 31) == 0) red[t >> 5] = s;
    __syncthreads();
    float S = 0.f;
#pragma unroll
    for (int w = 0; w < 8; w++) S += red[w];
    float inv = 1.f / S;
    for (int i = t; i < NN; i += 256) base[i] *= inv;
}

// ---------------- kernel 3: Lc[b,k,v] = sum_{u,m} k[b,u,k,m] v[b,u,v,m] ----------------
// grid (16 b, 8 m-splits of 392), 256 threads; atomicAdd into zeroed g_Lc.
__global__ void __launch_bounds__(256) lc_kernel() {
    const int b  = blockIdx.x;
    const int sp = blockIdx.y;
    __shared__ float ks[56 * 17];
    __shared__ float vs[56 * 65];
    const int t  = threadIdx.x;
    const int vc = t & 63;
    const int kg = t >> 6;      // 0..3 -> k = kg*4 + i

    float acc[4] = {0.f, 0.f, 0.f, 0.f};
    for (int u = 0; u < 4; u++) {
        for (int ch = 0; ch < 7; ch++) {
            int m0 = (sp * 7 + ch) * 56;
            __syncthreads();
            for (int s = t; s < 16 * 56; s += 256) {
                int kc = s / 56, m = s % 56;
                ks[m * 17 + kc] = g_k[(size_t)((b * 4 + u) * 16 + kc) * NN + m0 + m];
            }
            for (int s = t; s < 64 * 56; s += 256) {
                int c = s / 56, m = s % 56;
                vs[m * 65 + c] = g_v[(size_t)((b * 4 + u) * 64 + c) * NN + m0 + m];
            }
            __syncthreads();
            for (int m = 0; m < 56; m++) {
                float vvv = vs[m * 65 + vc];
#pragma unroll
                for (int i = 0; i < 4; i++) acc[i] += ks[m * 17 + kg * 4 + i] * vvv;
            }
        }
    }
#pragma unroll
    for (int i = 0; i < 4; i++)
        atomicAdd(&g_Lc[((size_t)b * 16 + kg * 4 + i) * DVV + vc], acc[i]);
}

// ---------------- kernel 4: fused 15x15 position conv + lambda contraction ----------------
// grid (32 v-pairs, 7 y-tiles of 8 rows, 16 b), 224 threads.
// Each thread: 2 x-positions x (v0,v1)-pair packed in f32x2, acc over k=16.
__global__ void __launch_bounds__(224, 2) lambda_main(
    const float* __restrict__ posw, const float* __restrict__ posb,
    float* __restrict__ out)
{
    __shared__ float vs[22 * 70 * 2];     // halo tile, (v0,v1) interleaved
    __shared__ float ws[225 * 32];        // per-u weights, dup'd pairs {wa,wa,wb,wb} x 8 kp
    __shared__ float lcs[32];             // Lc[b][k][v0/v1]
    __shared__ float pbs[16];             // pos_b

    const int vp = blockIdx.x;            // v-pair 0..31
    const int yt = blockIdx.y;            // y tile 0..6
    const int b  = blockIdx.z;
    const int t  = threadIdx.x;
    const int ty  = t / 28;               // 0..7 output row in tile
    const int txp = t % 28;               // x-pair 0..27 -> x = 2*txp, 2*txp+1
    const int y0 = yt * 8;

    if (t < 32) lcs[t] = g_Lc[((size_t)b * 16 + (t >> 1)) * DVV + vp * 2 + (t & 1)];
    if (t < 16) pbs[t] = posb[t];

    ull acc[32];
#pragma unroll
    for (int i = 0; i < 32; i++) acc[i] = 0ull;

    for (int u = 0; u < 4; u++) {
        __syncthreads();
        const float* v0p = g_v + (size_t)((b * 4 + u) * 64 + vp * 2) * NN;
        for (int s = t; s < 22 * 70; s += 224) {
            int yy = s / 70, xx = s % 70;
            int yi = y0 - 7 + yy, xi = xx - 7;
            float a = 0.f, c = 0.f;
            if (yi >= 0 && yi < HH && xi >= 0 && xi < WWID) {
                int o = yi * WWID + xi;
                a = v0p[o]; c = v0p[o + NN];
            }
            vs[2 * s] = a; vs[2 * s + 1] = c;
        }
        for (int s = t; s < 225 * 8; s += 224) {
            int tap = s >> 3, kp = s & 7;
            float wa = posw[(size_t)(2 * kp)     * 900 + u * 225 + tap];
            float wb = posw[(size_t)(2 * kp + 1) * 900 + u * 225 + tap];
            float* wp = ws + tap * 32 + kp * 4;
            wp[0] = wa; wp[1] = wa; wp[2] = wb; wp[3] = wb;
        }
        __syncthreads();

        const ull* vsp = (const ull*)vs;                 // index in (v-pair) units
        const ulonglong2* wsp = (const ulonglong2*)ws;   // index = tap*8 + kp
        for (int dy = 0; dy < 15; dy++) {
            int rowb = (ty + dy) * 70 + txp * 2;
#pragma unroll 3
            for (int dx = 0; dx < 15; dx++) {
                ull a0 = vsp[rowb + dx];
                ull a1 = vsp[rowb + dx + 1];
                const ulonglong2* wp = wsp + (dy * 15 + dx) * 8;
#pragma unroll
                for (int kp = 0; kp < 8; kp++) {
                    ulonglong2 w = wp[kp];
                    ffma2(acc[kp * 4 + 0], a0, w.x);
                    ffma2(acc[kp * 4 + 1], a1, w.x);
                    ffma2(acc[kp * 4 + 2], a0, w.y);
                    ffma2(acc[kp * 4 + 3], a1, w.y);
                }
            }
        }
    }

    // acc[k][pos] += Lc[b,k,v-pair] + pos_b[k]
#pragma unroll
    for (int kp = 0; kp < 8; kp++) {
        int k0 = 2 * kp, k1 = 2 * kp + 1;
        ull l0 = fpack(lcs[k0 * 2] + pbs[k0], lcs[k0 * 2 + 1] + pbs[k0]);
        ull l1 = fpack(lcs[k1 * 2] + pbs[k1], lcs[k1 * 2 + 1] + pbs[k1]);
        fadd2(acc[kp * 4 + 0], l0); fadd2(acc[kp * 4 + 1], l0);
        fadd2(acc[kp * 4 + 2], l1); fadd2(acc[kp * 4 + 3], l1);
    }

    // Y[b,n,h,v] = sum_k q[b,h,k,n] * (Lc + pos_b + Lp)[k,v,n]; write as [b,(h v),y,x]
    const int n = (y0 + ty) * WWID + txp * 2;
    const float* qb = g_q + (size_t)b * 64 * NN + n;
    float* ob = out + ((size_t)b * 256 + vp * 2) * NN + n;
#pragma unroll
    for (int h = 0; h < 4; h++) {
        ull ya = 0ull, yb = 0ull;
#pragma unroll
        for (int k = 0; k < 16; k++) {
            float2 qv = *(const float2*)&qb[(size_t)(h * 16 + k) * NN];
            int ai = (k >> 1) * 4 + (k & 1) * 2;
            ffma2(ya, acc[ai],     pack2(qv.x));
            ffma2(yb, acc[ai + 1], pack2(qv.y));
        }
        float y0l, y0h, y1l, y1h;
        funpack(ya, y0l, y0h);
        funpack(yb, y1l, y1h);
        float* o = ob + (size_t)h * 64 * NN;
        o[0] = y0l; o[NN] = y0h;       // pos0: v0, v1
        o[1] = y1l; o[NN + 1] = y1h;   // pos1: v0, v1
    }
}

// ---------------- launch ----------------
extern "C" void kernel_launch(void* const* d_in, const int* in_sizes, int n_in,
                              void* d_out, int out_size) {
    const float* x    = (const float*)d_in[0];
    const float* Wq   = (const float*)d_in[1];
    const float* Wk   = (const float*)d_in[2];
    const float* Wv   = (const float*)d_in[3];
    const float* posw = (const float*)d_in[4];
    const float* posb = (const float*)d_in[5];
    const float* gq   = (const float*)d_in[6];
    const float* bq   = (const float*)d_in[7];
    const float* mq   = (const float*)d_in[8];
    const float* vq   = (const float*)d_in[9];
    const float* gv   = (const float*)d_in[10];
    const float* bv   = (const float*)d_in[11];
    const float* mv   = (const float*)d_in[12];
    const float* vv   = (const float*)d_in[13];
    float* out = (float*)d_out;

    zero_lc_kernel<<<16, 1024>>>();
    proj_kernel<<<dim3(25, 6, 16), 256>>>(x, Wq, Wk, Wv,
                                          gq, bq, mq, vq, gv, bv, mv, vv);
    softmax_kernel<<<BB * 64, 256>>>();
    lc_kernel<<<dim3(16, 8), 256>>>();
    lambda_main<<<dim3(32, 7, 16), 224>>>(posw, posb, out);
}

// round 4
// speedup vs baseline: 1.0026x; 1.0026x over previous
#include <cuda_runtime.h>
#include <cuda_bf16.h>

// ---------------- problem constants ----------------
#define BB     16
#define CCH    256
#define HH     56
#define WWID   56
#define NN     3136          // 56*56
#define NHEADS 4
#define DK     16
#define DU     4
#define DVV    64
#define RR     15
// conv pad = 7

typedef unsigned long long ull;

// ---------------- scratch (device globals; no allocations allowed) ----------------
__device__ float g_q[BB * 64 * NN];    // [b][h*16+k][n]   (BN applied)
__device__ float g_k[BB * 64 * NN];    // [b][u*16+k][n]   (softmaxed in place)
__device__ float g_v[BB * 256 * NN];   // [b][u*64+v][n]   (BN applied)
__device__ float g_Lc[BB * DK * DVV];  // [b][k][v]

// ---------------- f32x2 helpers (sm_103a packed fp32 pipe) ----------------
__device__ __forceinline__ void ffma2(ull &d, ull a, ull b) {
    asm volatile("fma.rn.f32x2 %0, %1, %2, %0;" : "+l"(d) : "l"(a), "l"(b));
}
__device__ __forceinline__ void fadd2(ull &d, ull a) {
    asm volatile("add.rn.f32x2 %0, %0, %1;" : "+l"(d) : "l"(a));
}
__device__ __forceinline__ ull pack2(float x) {
    ull r; asm("mov.b64 %0, {%1, %1};" : "=l"(r) : "f"(x)); return r;
}
__device__ __forceinline__ ull fpack(float lo, float hi) {
    ull r; asm("mov.b64 %0, {%1, %2};" : "=l"(r) : "f"(lo), "f"(hi)); return r;
}
__device__ __forceinline__ void funpack(ull v, float &lo, float &hi) {
    asm("mov.b64 {%0, %1}, %2;" : "=f"(lo), "=f"(hi) : "l"(v));
}

// ---------------- kernel 0: zero Lc accumulator ----------------
__global__ void zero_lc_kernel() {
    int i = blockIdx.x * blockDim.x + threadIdx.x;
    if (i < BB * DK * DVV) g_Lc[i] = 0.f;
}

// ---------------- kernel 1: fused 1x1-conv projections + BatchNorm ----------------
// out[b, d, n] = sum_c x[b,c,n] * W[c,d], then BN (q and v only).
// grid (25 n-blocks of 128, 6 d-blocks of 64, 16 b), 256 threads.
__global__ void __launch_bounds__(256) proj_kernel(
    const float* __restrict__ x,
    const float* __restrict__ Wq, const float* __restrict__ Wk, const float* __restrict__ Wv,
    const float* __restrict__ gq, const float* __restrict__ bq,
    const float* __restrict__ mq, const float* __restrict__ vq,
    const float* __restrict__ gv, const float* __restrict__ bv,
    const float* __restrict__ mv, const float* __restrict__ vv)
{
    __shared__ float xs[32 * 128];
    __shared__ float Ws[32 * 64];

    const int b  = blockIdx.z;
    const int db = blockIdx.y;
    const int n0 = blockIdx.x * 128;
    const int t  = threadIdx.x;
    const int tx = t & 15;        // n-pair group
    const int ty = t >> 4;        // d group (4 channels each)

    const float* Wsrc; int dstride, dcol0;
    if (db == 0)      { Wsrc = Wq; dstride = 64;  dcol0 = 0; }
    else if (db == 1) { Wsrc = Wk; dstride = 64;  dcol0 = 0; }
    else              { Wsrc = Wv; dstride = 256; dcol0 = (db - 2) * 64; }

    ull acc[16];
#pragma unroll
    for (int i = 0; i < 16; i++) acc[i] = 0ull;

    for (int c0 = 0; c0 < CCH; c0 += 32) {
        __syncthreads();
        for (int s = t; s < 32 * 128; s += 256) {
            int cc = s >> 7, nn = s & 127;
            int g = n0 + nn;
            xs[s] = (g < NN) ? x[(size_t)(b * CCH + c0 + cc) * NN + g] : 0.f;
        }
        for (int s = t; s < 32 * 64; s += 256) {
            int cc = s >> 6, dd = s & 63;
            Ws[s] = Wsrc[(size_t)(c0 + cc) * dstride + dcol0 + dd];
        }
        __syncthreads();

#pragma unroll 8
        for (int ccl = 0; ccl < 32; ccl++) {
            ull xv[4];
#pragma unroll
            for (int j = 0; j < 4; j++)
                xv[j] = *(const ull*)&xs[ccl * 128 + ((tx + 16 * j) << 1)];
#pragma unroll
            for (int i = 0; i < 4; i++) {
                ull w2 = pack2(Ws[ccl * 64 + ty * 4 + i]);
#pragma unroll
                for (int j = 0; j < 4; j++) ffma2(acc[i * 4 + j], xv[j], w2);
            }
        }
    }

    // epilogue: BN + store
    float* dst;
    if (db == 0)      dst = g_q + (size_t)b * 64 * NN;
    else if (db == 1) dst = g_k + (size_t)b * 64 * NN;
    else              dst = g_v + ((size_t)b * 256 + dcol0) * NN;

    float sc[4], sh[4];
#pragma unroll
    for (int i = 0; i < 4; i++) {
        int d = ty * 4 + i;
        if (db == 0) {
            float inv = gq[d] * rsqrtf(vq[d] + 1e-5f);
            sc[i] = inv; sh[i] = bq[d] - mq[d] * inv;
        } else if (db == 1) {
            sc[i] = 1.f; sh[i] = 0.f;
        } else {
            int uvi = dcol0 + d;
            float inv = gv[uvi] * rsqrtf(vv[uvi] + 1e-5f);
            sc[i] = inv; sh[i] = bv[uvi] - mv[uvi] * inv;
        }
    }
#pragma unroll
    for (int i = 0; i < 4; i++) {
#pragma unroll
        for (int j = 0; j < 4; j++) {
            int n = n0 + ((tx + 16 * j) << 1);
            if (n < NN) {
                float lo, hi; funpack(acc[i * 4 + j], lo, hi);
                float* p = dst + (size_t)(ty * 4 + i) * NN + n;
                p[0] = lo * sc[i] + sh[i];
                p[1] = hi * sc[i] + sh[i];
            }
        }
    }
}

// ---------------- kernel 2: softmax over positions, in place on g_k ----------------
__global__ void __launch_bounds__(256) softmax_kernel() {
    const int row = blockIdx.x;                 // b*64 + u*16 + k
    float* base = g_k + (size_t)row * NN;
    const int t = threadIdx.x;
    __shared__ float red[8];

    float m = -3e38f;
    for (int i = t; i < NN; i += 256) m = fmaxf(m, base[i]);
#pragma unroll
    for (int o = 16; o; o >>= 1) m = fmaxf(m, __shfl_xor_sync(0xffffffffu, m, o));
    if ((t & 31) == 0) red[t >> 5] = m;
    __syncthreads();
    float mx = red[0];
#pragma unroll
    for (int w = 1; w < 8; w++) mx = fmaxf(mx, red[w]);
    __syncthreads();

    float s = 0.f;
    for (int i = t; i < NN; i += 256) {
        float e = expf(base[i] - mx);
        base[i] = e;
        s += e;
    }
#pragma unroll
    for (int o = 16; o; o >>= 1) s += __shfl_xor_sync(0xffffffffu, s, o);
    if ((t & 31) == 0) red[t >> 5] = s;
    __syncthreads();
    float S = 0.f;
#pragma unroll
    for (int w = 0; w < 8; w++) S += red[w];
    float inv = 1.f / S;
    for (int i = t; i < NN; i += 256) base[i] *= inv;
}

// ---------------- kernel 3: Lc[b,k,v] = sum_{u,m} k[b,u,k,m] v[b,u,v,m] ----------------
// grid (16 b, 8 m-splits of 392), 256 threads; atomicAdd into zeroed g_Lc.
__global__ void __launch_bounds__(256) lc_kernel() {
    const int b  = blockIdx.x;
    const int sp = blockIdx.y;
    __shared__ float ks[56 * 17];
    __shared__ float vs[56 * 65];
    const int t  = threadIdx.x;
    const int vc = t & 63;
    const int kg = t >> 6;      // 0..3 -> k = kg*4 + i

    float acc[4] = {0.f, 0.f, 0.f, 0.f};
    for (int u = 0; u < 4; u++) {
        for (int ch = 0; ch < 7; ch++) {
            int m0 = (sp * 7 + ch) * 56;
            __syncthreads();
            for (int s = t; s < 16 * 56; s += 256) {
                int kc = s / 56, m = s % 56;
                ks[m * 17 + kc] = g_k[(size_t)((b * 4 + u) * 16 + kc) * NN + m0 + m];
            }
            for (int s = t; s < 64 * 56; s += 256) {
                int c = s / 56, m = s % 56;
                vs[m * 65 + c] = g_v[(size_t)((b * 4 + u) * 64 + c) * NN + m0 + m];
            }
            __syncthreads();
            for (int m = 0; m < 56; m++) {
                float vvv = vs[m * 65 + vc];
#pragma unroll
                for (int i = 0; i < 4; i++) acc[i] += ks[m * 17 + kg * 4 + i] * vvv;
            }
        }
    }
#pragma unroll
    for (int i = 0; i < 4; i++)
        atomicAdd(&g_Lc[((size_t)b * 16 + kg * 4 + i) * DVV + vc], acc[i]);
}

// ---------------- kernel 4: fused 15x15 position conv + lambda contraction ----------------
// grid (32 v-pairs, 7 y-tiles of 8 rows, 16 b), 224 threads.
// Each thread: 2 x-positions x (v0,v1)-pair packed in f32x2, acc over k=16.
__global__ void __launch_bounds__(224, 2) lambda_main(
    const float* __restrict__ posw, const float* __restrict__ posb,
    float* __restrict__ out)
{
    __shared__ float vs[22 * 70 * 2];     // halo tile, (v0,v1) interleaved
    __shared__ float ws[225 * 32];        // per-u weights, dup'd pairs {wa,wa,wb,wb} x 8 kp
    __shared__ float lcs[32];             // Lc[b][k][v0/v1]
    __shared__ float pbs[16];             // pos_b

    const int vp = blockIdx.x;            // v-pair 0..31
    const int yt = blockIdx.y;            // y tile 0..6
    const int b  = blockIdx.z;
    const int t  = threadIdx.x;
    const int ty  = t / 28;               // 0..7 output row in tile
    const int txp = t % 28;               // x-pair 0..27 -> x = 2*txp, 2*txp+1
    const int y0 = yt * 8;

    if (t < 32) lcs[t] = g_Lc[((size_t)b * 16 + (t >> 1)) * DVV + vp * 2 + (t & 1)];
    if (t < 16) pbs[t] = posb[t];

    ull acc[32];
#pragma unroll
    for (int i = 0; i < 32; i++) acc[i] = 0ull;

    for (int u = 0; u < 4; u++) {
        __syncthreads();
        const float* v0p = g_v + (size_t)((b * 4 + u) * 64 + vp * 2) * NN;
        for (int s = t; s < 22 * 70; s += 224) {
            int yy = s / 70, xx = s % 70;
            int yi = y0 - 7 + yy, xi = xx - 7;
            float a = 0.f, c = 0.f;
            if (yi >= 0 && yi < HH && xi >= 0 && xi < WWID) {
                int o = yi * WWID + xi;
                a = v0p[o]; c = v0p[o + NN];
            }
            vs[2 * s] = a; vs[2 * s + 1] = c;
        }
        for (int s = t; s < 225 * 8; s += 224) {
            int tap = s >> 3, kp = s & 7;
            float wa = posw[(size_t)(2 * kp)     * 900 + u * 225 + tap];
            float wb = posw[(size_t)(2 * kp + 1) * 900 + u * 225 + tap];
            float* wp = ws + tap * 32 + kp * 4;
            wp[0] = wa; wp[1] = wa; wp[2] = wb; wp[3] = wb;
        }
        __syncthreads();

        const ull* vsp = (const ull*)vs;                 // index in (v-pair) units
        const ulonglong2* wsp = (const ulonglong2*)ws;   // index = tap*8 + kp
        for (int dy = 0; dy < 15; dy++) {
            int rowb = (ty + dy) * 70 + txp * 2;
#pragma unroll 3
            for (int dx = 0; dx < 15; dx++) {
                ull a0 = vsp[rowb + dx];
                ull a1 = vsp[rowb + dx + 1];
                const ulonglong2* wp = wsp + (dy * 15 + dx) * 8;
#pragma unroll
                for (int kp = 0; kp < 8; kp++) {
                    ulonglong2 w = wp[kp];
                    ffma2(acc[kp * 4 + 0], a0, w.x);
                    ffma2(acc[kp * 4 + 1], a1, w.x);
                    ffma2(acc[kp * 4 + 2], a0, w.y);
                    ffma2(acc[kp * 4 + 3], a1, w.y);
                }
            }
        }
    }

    // acc[k][pos] += Lc[b,k,v-pair] + pos_b[k]
#pragma unroll
    for (int kp = 0; kp < 8; kp++) {
        int k0 = 2 * kp, k1 = 2 * kp + 1;
        ull l0 = fpack(lcs[k0 * 2] + pbs[k0], lcs[k0 * 2 + 1] + pbs[k0]);
        ull l1 = fpack(lcs[k1 * 2] + pbs[k1], lcs[k1 * 2 + 1] + pbs[k1]);
        fadd2(acc[kp * 4 + 0], l0); fadd2(acc[kp * 4 + 1], l0);
        fadd2(acc[kp * 4 + 2], l1); fadd2(acc[kp * 4 + 3], l1);
    }

    // Y[b,n,h,v] = sum_k q[b,h,k,n] * (Lc + pos_b + Lp)[k,v,n]; write as [b,(h v),y,x]
    const int n = (y0 + ty) * WWID + txp * 2;
    const float* qb = g_q + (size_t)b * 64 * NN + n;
    float* ob = out + ((size_t)b * 256 + vp * 2) * NN + n;
#pragma unroll
    for (int h = 0; h < 4; h++) {
        ull ya = 0ull, yb = 0ull;
#pragma unroll
        for (int k = 0; k < 16; k++) {
            float2 qv = *(const float2*)&qb[(size_t)(h * 16 + k) * NN];
            int ai = (k >> 1) * 4 + (k & 1) * 2;
            ffma2(ya, acc[ai],     pack2(qv.x));
            ffma2(yb, acc[ai + 1], pack2(qv.y));
        }
        float y0l, y0h, y1l, y1h;
        funpack(ya, y0l, y0h);
        funpack(yb, y1l, y1h);
        float* o = ob + (size_t)h * 64 * NN;
        o[0] = y0l; o[NN] = y0h;       // pos0: v0, v1
        o[1] = y1l; o[NN + 1] = y1h;   // pos1: v0, v1
    }
}

// ---------------- launch ----------------
extern "C" void kernel_launch(void* const* d_in, const int* in_sizes, int n_in,
                              void* d_out, int out_size) {
    const float* x    = (const float*)d_in[0];
    const float* Wq   = (const float*)d_in[1];
    const float* Wk   = (const float*)d_in[2];
    const float* Wv   = (const float*)d_in[3];
    const float* posw = (const float*)d_in[4];
    const float* posb = (const float*)d_in[5];
    const float* gq   = (const float*)d_in[6];
    const float* bq   = (const float*)d_in[7];
    const float* mq   = (const float*)d_in[8];
    const float* vq   = (const float*)d_in[9];
    const float* gv   = (const float*)d_in[10];
    const float* bv   = (const float*)d_in[11];
    const float* mv   = (const float*)d_in[12];
    const float* vv   = (const float*)d_in[13];
    float* out = (float*)d_out;

    zero_lc_kernel<<<16, 1024>>>();
    proj_kernel<<<dim3(25, 6, 16), 256>>>(x, Wq, Wk, Wv,
                                          gq, bq, mq, vq, gv, bv, mv, vv);
    softmax_kernel<<<BB * 64, 256>>>();
    lc_kernel<<<dim3(16, 8), 256>>>();
    lambda_main<<<dim3(32, 7, 16), 224>>>(posw, posb, out);
}

// round 5
// speedup vs baseline: 1.1803x; 1.1773x over previous
#include <cuda_runtime.h>
#include <cuda_bf16.h>

// ---------------- problem constants ----------------
#define BB     16
#define CCH    256
#define HH     56
#define WWID   56
#define NN     3136          // 56*56
#define NHEADS 4
#define DK     16
#define DU     4
#define DVV    64
#define RR     15
// conv pad = 7

typedef unsigned long long ull;

// ---------------- scratch (device globals; no allocations allowed) ----------------
__device__ float g_q[BB * 64 * NN];    // [b][h*16+k][n]   (BN applied)
__device__ float g_k[BB * 64 * NN];    // [b][u*16+k][n]   (softmaxed in place)
__device__ float g_v[BB * 256 * NN];   // [b][u*64+v][n]   (BN applied)
__device__ float g_Lc[BB * DK * DVV];  // [b][k][v]

// ---------------- f32x2 helpers (sm_103a packed fp32 pipe) ----------------
__device__ __forceinline__ void ffma2(ull &d, ull a, ull b) {
    asm volatile("fma.rn.f32x2 %0, %1, %2, %0;" : "+l"(d) : "l"(a), "l"(b));
}
__device__ __forceinline__ ull pack2(float x) {
    ull r; asm("mov.b64 %0, {%1, %1};" : "=l"(r) : "f"(x)); return r;
}
__device__ __forceinline__ ull fpack(float lo, float hi) {
    ull r; asm("mov.b64 %0, {%1, %2};" : "=l"(r) : "f"(lo), "f"(hi)); return r;
}
__device__ __forceinline__ void funpack(ull v, float &lo, float &hi) {
    asm("mov.b64 {%0, %1}, %2;" : "=f"(lo), "=f"(hi) : "l"(v));
}

// ---------------- kernel 0: zero Lc accumulator ----------------
__global__ void zero_lc_kernel() {
    int i = blockIdx.x * blockDim.x + threadIdx.x;
    if (i < BB * DK * DVV) g_Lc[i] = 0.f;
}

// ---------------- kernel 1: fused 1x1-conv projections + BatchNorm ----------------
__global__ void __launch_bounds__(256) proj_kernel(
    const float* __restrict__ x,
    const float* __restrict__ Wq, const float* __restrict__ Wk, const float* __restrict__ Wv,
    const float* __restrict__ gq, const float* __restrict__ bq,
    const float* __restrict__ mq, const float* __restrict__ vq,
    const float* __restrict__ gv, const float* __restrict__ bv,
    const float* __restrict__ mv, const float* __restrict__ vv)
{
    __shared__ float xs[32 * 128];
    __shared__ float Ws[32 * 64];

    const int b  = blockIdx.z;
    const int db = blockIdx.y;
    const int n0 = blockIdx.x * 128;
    const int t  = threadIdx.x;
    const int tx = t & 15;
    const int ty = t >> 4;

    const float* Wsrc; int dstride, dcol0;
    if (db == 0)      { Wsrc = Wq; dstride = 64;  dcol0 = 0; }
    else if (db == 1) { Wsrc = Wk; dstride = 64;  dcol0 = 0; }
    else              { Wsrc = Wv; dstride = 256; dcol0 = (db - 2) * 64; }

    ull acc[16];
#pragma unroll
    for (int i = 0; i < 16; i++) acc[i] = 0ull;

    for (int c0 = 0; c0 < CCH; c0 += 32) {
        __syncthreads();
        for (int s = t; s < 32 * 128; s += 256) {
            int cc = s >> 7, nn = s & 127;
            int g = n0 + nn;
            xs[s] = (g < NN) ? x[(size_t)(b * CCH + c0 + cc) * NN + g] : 0.f;
        }
        for (int s = t; s < 32 * 64; s += 256) {
            int cc = s >> 6, dd = s & 63;
            Ws[s] = Wsrc[(size_t)(c0 + cc) * dstride + dcol0 + dd];
        }
        __syncthreads();

#pragma unroll 8
        for (int ccl = 0; ccl < 32; ccl++) {
            ull xv[4];
#pragma unroll
            for (int j = 0; j < 4; j++)
                xv[j] = *(const ull*)&xs[ccl * 128 + ((tx + 16 * j) << 1)];
#pragma unroll
            for (int i = 0; i < 4; i++) {
                ull w2 = pack2(Ws[ccl * 64 + ty * 4 + i]);
#pragma unroll
                for (int j = 0; j < 4; j++) ffma2(acc[i * 4 + j], xv[j], w2);
            }
        }
    }

    float* dst;
    if (db == 0)      dst = g_q + (size_t)b * 64 * NN;
    else if (db == 1) dst = g_k + (size_t)b * 64 * NN;
    else              dst = g_v + ((size_t)b * 256 + dcol0) * NN;

    float sc[4], sh[4];
#pragma unroll
    for (int i = 0; i < 4; i++) {
        int d = ty * 4 + i;
        if (db == 0) {
            float inv = gq[d] * rsqrtf(vq[d] + 1e-5f);
            sc[i] = inv; sh[i] = bq[d] - mq[d] * inv;
        } else if (db == 1) {
            sc[i] = 1.f; sh[i] = 0.f;
        } else {
            int uvi = dcol0 + d;
            float inv = gv[uvi] * rsqrtf(vv[uvi] + 1e-5f);
            sc[i] = inv; sh[i] = bv[uvi] - mv[uvi] * inv;
        }
    }
#pragma unroll
    for (int i = 0; i < 4; i++) {
#pragma unroll
        for (int j = 0; j < 4; j++) {
            int n = n0 + ((tx + 16 * j) << 1);
            if (n < NN) {
                float lo, hi; funpack(acc[i * 4 + j], lo, hi);
                float* p = dst + (size_t)(ty * 4 + i) * NN + n;
                p[0] = lo * sc[i] + sh[i];
                p[1] = hi * sc[i] + sh[i];
            }
        }
    }
}

// ---------------- kernel 2: softmax over positions, in place on g_k ----------------
__global__ void __launch_bounds__(256) softmax_kernel() {
    const int row = blockIdx.x;
    float* base = g_k + (size_t)row * NN;
    const int t = threadIdx.x;
    __shared__ float red[8];

    float m = -3e38f;
    for (int i = t; i < NN; i += 256) m = fmaxf(m, base[i]);
#pragma unroll
    for (int o = 16; o; o >>= 1) m = fmaxf(m, __shfl_xor_sync(0xffffffffu, m, o));
    if ((t & 31) == 0) red[t >> 5] = m;
    __syncthreads();
    float mx = red[0];
#pragma unroll
    for (int w = 1; w < 8; w++) mx = fmaxf(mx, red[w]);
    __syncthreads();

    float s = 0.f;
    for (int i = t; i < NN; i += 256) {
        float e = expf(base[i] - mx);
        base[i] = e;
        s += e;
    }
#pragma unroll
    for (int o = 16; o; o >>= 1) s += __shfl_xor_sync(0xffffffffu, s, o);
    if ((t & 31) == 0) red[t >> 5] = s;
    __syncthreads();
    float S = 0.f;
#pragma unroll
    for (int w = 0; w < 8; w++) S += red[w];
    float inv = 1.f / S;
    for (int i = t; i < NN; i += 256) base[i] *= inv;
}

// ---------------- kernel 3: Lc[b,k,v] — 7x more blocks (was latency-bound) ----------
// grid (16 b, 56 m-splits of 56), 256 threads; atomicAdd into zeroed g_Lc.
__global__ void __launch_bounds__(256) lc_kernel() {
    const int b  = blockIdx.x;
    const int sp = blockIdx.y;
    __shared__ float ks[56 * 17];
    __shared__ float vs[56 * 65];
    const int t  = threadIdx.x;
    const int vc = t & 63;
    const int kg = t >> 6;

    const int m0 = sp * 56;
    float acc[4] = {0.f, 0.f, 0.f, 0.f};
    for (int u = 0; u < 4; u++) {
        __syncthreads();
        for (int s = t; s < 16 * 56; s += 256) {
            int kc = s / 56, m = s % 56;
            ks[m * 17 + kc] = g_k[(size_t)((b * 4 + u) * 16 + kc) * NN + m0 + m];
        }
        for (int s = t; s < 64 * 56; s += 256) {
            int c = s / 56, m = s % 56;
            vs[m * 65 + c] = g_v[(size_t)((b * 4 + u) * 64 + c) * NN + m0 + m];
        }
        __syncthreads();
        for (int m = 0; m < 56; m++) {
            float vvv = vs[m * 65 + vc];
#pragma unroll
            for (int i = 0; i < 4; i++) acc[i] += ks[m * 17 + kg * 4 + i] * vvv;
        }
    }
#pragma unroll
    for (int i = 0; i < 4; i++)
        atomicAdd(&g_Lc[((size_t)b * 16 + kg * 4 + i) * DVV + vc], acc[i]);
}

// ---------------- kernel 4: restructured lambda (qw = q*w first; 3.2x fewer FLOPs) ----
// Yp[h,v,n] = sum_{u,dy,dx} qw[h,dx,n] * v[u,v,n+shift];  qw = sum_k q[h,k,n] w[k,u,dy,dx]
// grid (56 y, 16 b), 256 threads = 8 warps x 7 x-cols; lane = v-pair (f32x2).
// Dynamic smem layout (floats):
//   qs   [64][58]      @ 0      (q row, padded)
//   wsu  [16][225]     @ 3712   (weights for current u)
//   vrow [70][66]      @ 7312   (one v row, [xpos][v], zero-padded halo)
//   qwd  [15][56][8]   @ 11932  (qw h-duplicated quads {h0,h0,h1,h1,h2,h2,h3,h3})
//   lcp  [16][64]      @ 18652  (Lc + pos_b)
#define LSM_QS   0
#define LSM_WSU  3712
#define LSM_VROW 7312
#define LSM_QWD  11932
#define LSM_LCP  18652
#define LSM_TOTAL (19676 * 4)

__global__ void __launch_bounds__(256, 2) lambda_main2(
    const float* __restrict__ posw, const float* __restrict__ posb,
    float* __restrict__ out)
{
    extern __shared__ float sm[];
    float* qs   = sm + LSM_QS;
    float* wsu  = sm + LSM_WSU;
    float* vrow = sm + LSM_VROW;
    float* qwd  = sm + LSM_QWD;
    float* lcp  = sm + LSM_LCP;

    const int y    = blockIdx.x;
    const int b    = blockIdx.y;
    const int t    = threadIdx.x;
    const int w    = t >> 5;
    const int lane = t & 31;

    // one-time staging: q row, Lc'+pos_b, zero vrow (pads stay zero forever)
    for (int s = t; s < 64 * 14; s += 256) {
        int ch = s / 14, x4 = s % 14;
        float4 v4 = *(const float4*)(g_q + ((size_t)(b * 64 + ch)) * NN + y * 56 + x4 * 4);
        float* d = qs + ch * 58 + x4 * 4;
        d[0] = v4.x; d[1] = v4.y; d[2] = v4.z; d[3] = v4.w;
    }
    for (int s = t; s < 1024; s += 256) {
        int k = s >> 6;
        lcp[s] = g_Lc[(size_t)(b * 16) * 64 + s] + posb[k];
    }
    for (int s = t; s < 70 * 66; s += 256) vrow[s] = 0.f;

    ull acc[4][7];
#pragma unroll
    for (int h = 0; h < 4; h++)
#pragma unroll
        for (int xi = 0; xi < 7; xi++) acc[h][xi] = 0ull;

    for (int u = 0; u < 4; u++) {
        __syncthreads();                       // prev phase1/2 done -> wsu safe to overwrite
        for (int s = t; s < 3600; s += 256)    // wsu[k][tap]
            wsu[s] = posw[(size_t)(s / 225) * 900 + u * 225 + (s % 225)];

        for (int dy = 0; dy < 15; dy++) {
            const int row = y + dy - 7;
            if (row < 0 || row >= HH) continue;   // uniform skip: contributes zero
            __syncthreads();                       // prev phase2 done; wsu visible (1st iter)

            // stage v row: vrow[(x+7)*66 + v]
            const float* vsrc = g_v + ((size_t)((b * 4 + u) * 64)) * NN + row * 56;
            for (int s = t; s < 64 * 14; s += 256) {
                int v = s / 14, x4 = s % 14;
                float4 v4 = *(const float4*)(vsrc + (size_t)v * NN + x4 * 4);
                float* d = vrow + (x4 * 4 + 7) * 66 + v;
                d[0] = v4.x; d[66] = v4.y; d[132] = v4.z; d[198] = v4.w;
            }

            // phase 1: qw[h,dx,x] = sum_k q[h,k,x]*w[k,u,dy,dx], stored h-dup'd
            const int tapb = dy * 15;
            for (int idx = t; idx < 1680; idx += 256) {
                int xp = idx % 28;
                int hd = idx / 28;
                int h  = hd / 15, dx = hd % 15;
                const float* qrow = qs + (h * 16) * 58 + 2 * xp;
                const float* wr   = wsu + tapb + dx;
                ull a = 0ull;
#pragma unroll
                for (int k = 0; k < 16; k++)
                    ffma2(a, *(const ull*)(qrow + k * 58), pack2(wr[k * 225]));
                float lo, hi; funpack(a, lo, hi);
                float* dstp = qwd + (size_t)(dx * 56 + 2 * xp) * 8 + 2 * h;
                *(ull*)(dstp)     = fpack(lo, lo);
                *(ull*)(dstp + 8) = fpack(hi, hi);
            }
            __syncthreads();

            // phase 2: acc[h][xi] += qw ⊙ v-pair
            for (int dx = 0; dx < 15; dx++) {
                const ulonglong2* qq = (const ulonglong2*)(qwd + (size_t)(dx * 56 + 7 * w) * 8);
                const ull* vb = (const ull*)vrow + (7 * w + dx) * 33 + lane;
#pragma unroll
                for (int xi = 0; xi < 7; xi++) {
                    ull a = vb[xi * 33];
                    ulonglong2 q01 = qq[2 * xi];
                    ulonglong2 q23 = qq[2 * xi + 1];
                    ffma2(acc[0][xi], a, q01.x);
                    ffma2(acc[1][xi], a, q01.y);
                    ffma2(acc[2][xi], a, q23.x);
                    ffma2(acc[3][xi], a, q23.y);
                }
            }
        }
    }

    // epilogue: Y = acc + sum_k q[h,k,n]*(Lc[k,v]+pos_b[k]); transpose via smem, store
    __syncthreads();
    float* ybuf = qwd;   // reuse, [64][56]
    ull L[16];
#pragma unroll
    for (int k = 0; k < 16; k++) L[k] = *(const ull*)(lcp + k * 64 + 2 * lane);

    const int xbase = 7 * w;
    for (int h = 0; h < 4; h++) {
#pragma unroll
        for (int xi = 0; xi < 7; xi++) {
            ull yv = acc[h][xi];
            const float* qcol = qs + (h * 16) * 58 + xbase + xi;
#pragma unroll
            for (int k = 0; k < 16; k++) ffma2(yv, pack2(qcol[k * 58]), L[k]);
            float lo, hi; funpack(yv, lo, hi);
            ybuf[(2 * lane)     * 56 + xbase + xi] = lo;
            ybuf[(2 * lane + 1) * 56 + xbase + xi] = hi;
        }
        __syncthreads();
        float* obase = out + ((size_t)(b * 256 + h * 64)) * NN + y * 56;
        for (int s = t; s < 64 * 14; s += 256) {
            int v = s / 14, x4 = s % 14;
            const float* sb = ybuf + v * 56 + x4 * 4;
            float4 v4; v4.x = sb[0]; v4.y = sb[1]; v4.z = sb[2]; v4.w = sb[3];
            *(float4*)(obase + (size_t)v * NN + x4 * 4) = v4;
        }
        __syncthreads();
    }
}

// ---------------- launch ----------------
extern "C" void kernel_launch(void* const* d_in, const int* in_sizes, int n_in,
                              void* d_out, int out_size) {
    const float* x    = (const float*)d_in[0];
    const float* Wq   = (const float*)d_in[1];
    const float* Wk   = (const float*)d_in[2];
    const float* Wv   = (const float*)d_in[3];
    const float* posw = (const float*)d_in[4];
    const float* posb = (const float*)d_in[5];
    const float* gq   = (const float*)d_in[6];
    const float* bq   = (const float*)d_in[7];
    const float* mq   = (const float*)d_in[8];
    const float* vq   = (const float*)d_in[9];
    const float* gv   = (const float*)d_in[10];
    const float* bv   = (const float*)d_in[11];
    const float* mv   = (const float*)d_in[12];
    const float* vv   = (const float*)d_in[13];
    float* out = (float*)d_out;

    cudaFuncSetAttribute(lambda_main2,
                         cudaFuncAttributeMaxDynamicSharedMemorySize, LSM_TOTAL);

    zero_lc_kernel<<<16, 1024>>>();
    proj_kernel<<<dim3(25, 6, 16), 256>>>(x, Wq, Wk, Wv,
                                          gq, bq, mq, vq, gv, bv, mv, vv);
    softmax_kernel<<<BB * 64, 256>>>();
    lc_kernel<<<dim3(16, 56), 256>>>();
    lambda_main2<<<dim3(56, 16), 256, LSM_TOTAL>>>(posw, posb, out);
}

// round 6
// speedup vs baseline: 1.4131x; 1.1972x over previous
#include <cuda_runtime.h>
#include <cuda_bf16.h>

// ---------------- problem constants ----------------
#define BB     16
#define CCH    256
#define HH     56
#define WWID   56
#define NN     3136          // 56*56
#define NHEADS 4
#define DK     16
#define DU     4
#define DVV    64
#define RR     15
// conv pad = 7

typedef unsigned long long ull;

// ---------------- scratch (device globals; no allocations allowed) ----------------
__device__ float g_q[BB * 64 * NN];    // [b][h*16+k][n]   (BN applied)
__device__ float g_k[BB * 64 * NN];    // [b][u*16+k][n]   (softmaxed in place)
__device__ float g_v[BB * 256 * NN];   // [b][u*64+v][n]   (BN applied)
__device__ float g_Lc[BB * DK * DVV];  // [b][k][v]

// ---------------- f32x2 helpers (sm_103a packed fp32 pipe) ----------------
__device__ __forceinline__ void ffma2(ull &d, ull a, ull b) {
    asm volatile("fma.rn.f32x2 %0, %1, %2, %0;" : "+l"(d) : "l"(a), "l"(b));
}
__device__ __forceinline__ ull pack2(float x) {
    ull r; asm("mov.b64 %0, {%1, %1};" : "=l"(r) : "f"(x)); return r;
}
__device__ __forceinline__ ull fpack(float lo, float hi) {
    ull r; asm("mov.b64 %0, {%1, %2};" : "=l"(r) : "f"(lo), "f"(hi)); return r;
}
__device__ __forceinline__ void funpack(ull v, float &lo, float &hi) {
    asm("mov.b64 {%0, %1}, %2;" : "=f"(lo), "=f"(hi) : "l"(v));
}

// ---------------- kernel 0: zero Lc accumulator ----------------
__global__ void zero_lc_kernel() {
    int i = blockIdx.x * blockDim.x + threadIdx.x;
    if (i < BB * DK * DVV) g_Lc[i] = 0.f;
}

// ---------------- kernel 1: fused 1x1-conv projections + BatchNorm ----------------
__global__ void __launch_bounds__(256) proj_kernel(
    const float* __restrict__ x,
    const float* __restrict__ Wq, const float* __restrict__ Wk, const float* __restrict__ Wv,
    const float* __restrict__ gq, const float* __restrict__ bq,
    const float* __restrict__ mq, const float* __restrict__ vq,
    const float* __restrict__ gv, const float* __restrict__ bv,
    const float* __restrict__ mv, const float* __restrict__ vv)
{
    __shared__ float xs[32 * 128];
    __shared__ float Ws[32 * 64];

    const int b  = blockIdx.z;
    const int db = blockIdx.y;
    const int n0 = blockIdx.x * 128;
    const int t  = threadIdx.x;
    const int tx = t & 15;
    const int ty = t >> 4;

    const float* Wsrc; int dstride, dcol0;
    if (db == 0)      { Wsrc = Wq; dstride = 64;  dcol0 = 0; }
    else if (db == 1) { Wsrc = Wk; dstride = 64;  dcol0 = 0; }
    else              { Wsrc = Wv; dstride = 256; dcol0 = (db - 2) * 64; }

    ull acc[16];
#pragma unroll
    for (int i = 0; i < 16; i++) acc[i] = 0ull;

    for (int c0 = 0; c0 < CCH; c0 += 32) {
        __syncthreads();
        for (int s = t; s < 32 * 128; s += 256) {
            int cc = s >> 7, nn = s & 127;
            int g = n0 + nn;
            xs[s] = (g < NN) ? x[(size_t)(b * CCH + c0 + cc) * NN + g] : 0.f;
        }
        for (int s = t; s < 32 * 64; s += 256) {
            int cc = s >> 6, dd = s & 63;
            Ws[s] = Wsrc[(size_t)(c0 + cc) * dstride + dcol0 + dd];
        }
        __syncthreads();

#pragma unroll 8
        for (int ccl = 0; ccl < 32; ccl++) {
            ull xv[4];
#pragma unroll
            for (int j = 0; j < 4; j++)
                xv[j] = *(const ull*)&xs[ccl * 128 + ((tx + 16 * j) << 1)];
#pragma unroll
            for (int i = 0; i < 4; i++) {
                ull w2 = pack2(Ws[ccl * 64 + ty * 4 + i]);
#pragma unroll
                for (int j = 0; j < 4; j++) ffma2(acc[i * 4 + j], xv[j], w2);
            }
        }
    }

    float* dst;
    if (db == 0)      dst = g_q + (size_t)b * 64 * NN;
    else if (db == 1) dst = g_k + (size_t)b * 64 * NN;
    else              dst = g_v + ((size_t)b * 256 + dcol0) * NN;

    float sc[4], sh[4];
#pragma unroll
    for (int i = 0; i < 4; i++) {
        int d = ty * 4 + i;
        if (db == 0) {
            float inv = gq[d] * rsqrtf(vq[d] + 1e-5f);
            sc[i] = inv; sh[i] = bq[d] - mq[d] * inv;
        } else if (db == 1) {
            sc[i] = 1.f; sh[i] = 0.f;
        } else {
            int uvi = dcol0 + d;
            float inv = gv[uvi] * rsqrtf(vv[uvi] + 1e-5f);
            sc[i] = inv; sh[i] = bv[uvi] - mv[uvi] * inv;
        }
    }
#pragma unroll
    for (int i = 0; i < 4; i++) {
#pragma unroll
        for (int j = 0; j < 4; j++) {
            int n = n0 + ((tx + 16 * j) << 1);
            if (n < NN) {
                float lo, hi; funpack(acc[i * 4 + j], lo, hi);
                float* p = dst + (size_t)(ty * 4 + i) * NN + n;
                p[0] = lo * sc[i] + sh[i];
                p[1] = hi * sc[i] + sh[i];
            }
        }
    }
}

// ---------------- kernel 2: softmax over positions, in place on g_k ----------------
__global__ void __launch_bounds__(256) softmax_kernel() {
    const int row = blockIdx.x;
    float* base = g_k + (size_t)row * NN;
    const int t = threadIdx.x;
    __shared__ float red[8];

    float m = -3e38f;
    for (int i = t; i < NN; i += 256) m = fmaxf(m, base[i]);
#pragma unroll
    for (int o = 16; o; o >>= 1) m = fmaxf(m, __shfl_xor_sync(0xffffffffu, m, o));
    if ((t & 31) == 0) red[t >> 5] = m;
    __syncthreads();
    float mx = red[0];
#pragma unroll
    for (int w = 1; w < 8; w++) mx = fmaxf(mx, red[w]);
    __syncthreads();

    float s = 0.f;
    for (int i = t; i < NN; i += 256) {
        float e = expf(base[i] - mx);
        base[i] = e;
        s += e;
    }
#pragma unroll
    for (int o = 16; o; o >>= 1) s += __shfl_xor_sync(0xffffffffu, s, o);
    if ((t & 31) == 0) red[t >> 5] = s;
    __syncthreads();
    float S = 0.f;
#pragma unroll
    for (int w = 0; w < 8; w++) S += red[w];
    float inv = 1.f / S;
    for (int i = t; i < NN; i += 256) base[i] *= inv;
}

// ---------------- kernel 3: Lc[b,k,v] ----------------
__global__ void __launch_bounds__(256) lc_kernel() {
    const int b  = blockIdx.x;
    const int sp = blockIdx.y;
    __shared__ float ks[56 * 17];
    __shared__ float vs[56 * 65];
    const int t  = threadIdx.x;
    const int vc = t & 63;
    const int kg = t >> 6;

    const int m0 = sp * 56;
    float acc[4] = {0.f, 0.f, 0.f, 0.f};
    for (int u = 0; u < 4; u++) {
        __syncthreads();
        for (int s = t; s < 16 * 56; s += 256) {
            int kc = s / 56, m = s % 56;
            ks[m * 17 + kc] = g_k[(size_t)((b * 4 + u) * 16 + kc) * NN + m0 + m];
        }
        for (int s = t; s < 64 * 56; s += 256) {
            int c = s / 56, m = s % 56;
            vs[m * 65 + c] = g_v[(size_t)((b * 4 + u) * 64 + c) * NN + m0 + m];
        }
        __syncthreads();
        for (int m = 0; m < 56; m++) {
            float vvv = vs[m * 65 + vc];
#pragma unroll
            for (int i = 0; i < 4; i++) acc[i] += ks[m * 17 + kg * 4 + i] * vvv;
        }
    }
#pragma unroll
    for (int i = 0; i < 4; i++)
        atomicAdd(&g_Lc[((size_t)b * 16 + kg * 4 + i) * DVV + vc], acc[i]);
}

// ---------------- kernel 4: lambda, LDS-traffic-minimized ----------------
// Same algebra as R5 (qw = q*w contracted first), but:
//  - phase 1: warp = (h, dx-half), lane = x-pair; q in registers, reused over dx;
//    w reads are warp-uniform broadcasts; qw stored in quad layout
//    qwd[dx][x][{h0h0,h1h1,h2h2,h3h3}] (2-way conflict stores, LDS.128 bcast reads)
//  - phase 2: v window in registers (two 14-reg halves), so v smem reads drop
//    from 105 to 27 LDS.64 per warp per (u,dy).
// Dynamic smem layout (floats):
//   qs   [64][58]        @ 0
//   wsu  [16][225]       @ 3712
//   vrow [70][66]        @ 7312   (one v row, [xpos][v], zero-padded halo)
//   qwd  ull[15][56][4]  @ 11932  (6720 floats)
//   lcp  [16][64]        @ 18652
#define LSM_QS   0
#define LSM_WSU  3712
#define LSM_VROW 7312
#define LSM_QWD  11932
#define LSM_LCP  18652
#define LSM_TOTAL (19676 * 4)

__global__ void __launch_bounds__(256, 2) lambda_main3(
    const float* __restrict__ posw, const float* __restrict__ posb,
    float* __restrict__ out)
{
    extern __shared__ float sm[];
    float* qs   = sm + LSM_QS;
    float* wsu  = sm + LSM_WSU;
    float* vrow = sm + LSM_VROW;
    float* qwdf = sm + LSM_QWD;
    float* lcp  = sm + LSM_LCP;
    ull* qwd = (ull*)qwdf;

    const int y    = blockIdx.x;
    const int b    = blockIdx.y;
    const int t    = threadIdx.x;
    const int w    = t >> 5;
    const int lane = t & 31;
    // phase-1 role: warp -> (h, dx half)
    const int ph   = w >> 1;
    const int pd0  = (w & 1) ? 8 : 0;
    const int pdn  = (w & 1) ? 7 : 8;

    // one-time staging
    for (int s = t; s < 64 * 14; s += 256) {
        int ch = s / 14, x4 = s % 14;
        float4 v4 = *(const float4*)(g_q + ((size_t)(b * 64 + ch)) * NN + y * 56 + x4 * 4);
        float* d = qs + ch * 58 + x4 * 4;
        d[0] = v4.x; d[1] = v4.y; d[2] = v4.z; d[3] = v4.w;
    }
    for (int s = t; s < 1024; s += 256) {
        int k = s >> 6;
        lcp[s] = g_Lc[(size_t)(b * 16) * 64 + s] + posb[k];
    }
    for (int s = t; s < 70 * 66; s += 256) vrow[s] = 0.f;

    ull acc[4][7];
#pragma unroll
    for (int h = 0; h < 4; h++)
#pragma unroll
        for (int xi = 0; xi < 7; xi++) acc[h][xi] = 0ull;

    for (int u = 0; u < 4; u++) {
        __syncthreads();                       // prev phase2 done -> wsu safe
        for (int s = t; s < 3600; s += 256)    // wsu[k][tap]
            wsu[s] = posw[(size_t)(s / 225) * 900 + u * 225 + (s % 225)];

        for (int dy = 0; dy < 15; dy++) {
            const int row = y + dy - 7;
            if (row < 0 || row >= HH) continue;   // uniform skip
            __syncthreads();                      // prev phase2 done; wsu visible

            // stage v row: vrow[(x+7)*66 + v]
            const float* vsrc = g_v + ((size_t)((b * 4 + u) * 64)) * NN + row * 56;
            for (int s = t; s < 64 * 14; s += 256) {
                int v = s / 14, x4 = s % 14;
                float4 v4 = *(const float4*)(vsrc + (size_t)v * NN + x4 * 4);
                float* d = vrow + (x4 * 4 + 7) * 66 + v;
                d[0] = v4.x; d[66] = v4.y; d[132] = v4.z; d[198] = v4.w;
            }

            // phase 1: qw[h,dx,x] = sum_k q[h,k,x] * w[k,dy*15+dx]
            if (lane < 28) {
                ull qr[16];
                const float* qrow = qs + (ph * 16) * 58 + 2 * lane;
#pragma unroll
                for (int k = 0; k < 16; k++) qr[k] = *(const ull*)(qrow + k * 58);
                const float* wr = wsu + dy * 15 + pd0;
                for (int dxi = 0; dxi < pdn; dxi++) {
                    ull a = 0ull;
#pragma unroll
                    for (int k = 0; k < 16; k++)
                        ffma2(a, qr[k], pack2(wr[k * 225 + dxi]));
                    float lo, hi; funpack(a, lo, hi);
                    const int dx = pd0 + dxi;
                    qwd[(dx * 56 + 2 * lane)     * 4 + ph] = fpack(lo, lo);
                    qwd[(dx * 56 + 2 * lane + 1) * 4 + ph] = fpack(hi, hi);
                }
            }
            __syncthreads();

            // phase 2: acc[h][xi] += qw[h,dx,7w+xi] * v[7w+xi+dx]
            const ull* vbase = (const ull*)vrow + 7 * w * 33 + lane;
            {
                ull vwin[14];
#pragma unroll
                for (int i = 0; i < 14; i++) vwin[i] = vbase[i * 33];
#pragma unroll
                for (int dx = 0; dx < 8; dx++) {
                    const ulonglong2* qq = (const ulonglong2*)qwd + (dx * 56 + 7 * w) * 2;
#pragma unroll
                    for (int xi = 0; xi < 7; xi++) {
                        ulonglong2 q01 = qq[2 * xi];
                        ulonglong2 q23 = qq[2 * xi + 1];
                        ull a = vwin[xi + dx];
                        ffma2(acc[0][xi], a, q01.x);
                        ffma2(acc[1][xi], a, q01.y);
                        ffma2(acc[2][xi], a, q23.x);
                        ffma2(acc[3][xi], a, q23.y);
                    }
                }
            }
            {
                ull vwin[13];
#pragma unroll
                for (int i = 0; i < 13; i++) vwin[i] = vbase[(8 + i) * 33];
#pragma unroll
                for (int dx2 = 0; dx2 < 7; dx2++) {
                    const int dx = 8 + dx2;
                    const ulonglong2* qq = (const ulonglong2*)qwd + (dx * 56 + 7 * w) * 2;
#pragma unroll
                    for (int xi = 0; xi < 7; xi++) {
                        ulonglong2 q01 = qq[2 * xi];
                        ulonglong2 q23 = qq[2 * xi + 1];
                        ull a = vwin[xi + dx2];
                        ffma2(acc[0][xi], a, q01.x);
                        ffma2(acc[1][xi], a, q01.y);
                        ffma2(acc[2][xi], a, q23.x);
                        ffma2(acc[3][xi], a, q23.y);
                    }
                }
            }
        }
    }

    // epilogue: Y = acc + sum_k q[h,k,n]*(Lc[k,v]+pos_b[k]); transpose via smem
    __syncthreads();
    float* ybuf = qwdf;   // reuse, [64][56]
    ull L[16];
#pragma unroll
    for (int k = 0; k < 16; k++) L[k] = *(const ull*)(lcp + k * 64 + 2 * lane);

    const int xbase = 7 * w;
    for (int h = 0; h < 4; h++) {
#pragma unroll
        for (int xi = 0; xi < 7; xi++) {
            ull yv = acc[h][xi];
            const float* qcol = qs + (h * 16) * 58 + xbase + xi;
#pragma unroll
            for (int k = 0; k < 16; k++) ffma2(yv, pack2(qcol[k * 58]), L[k]);
            float lo, hi; funpack(yv, lo, hi);
            ybuf[(2 * lane)     * 56 + xbase + xi] = lo;
            ybuf[(2 * lane + 1) * 56 + xbase + xi] = hi;
        }
        __syncthreads();
        float* obase = out + ((size_t)(b * 256 + h * 64)) * NN + y * 56;
        for (int s = t; s < 64 * 14; s += 256) {
            int v = s / 14, x4 = s % 14;
            const float* sb = ybuf + v * 56 + x4 * 4;
            float4 v4; v4.x = sb[0]; v4.y = sb[1]; v4.z = sb[2]; v4.w = sb[3];
            *(float4*)(obase + (size_t)v * NN + x4 * 4) = v4;
        }
        __syncthreads();
    }
}

// ---------------- launch ----------------
extern "C" void kernel_launch(void* const* d_in, const int* in_sizes, int n_in,
                              void* d_out, int out_size) {
    const float* x    = (const float*)d_in[0];
    const float* Wq   = (const float*)d_in[1];
    const float* Wk   = (const float*)d_in[2];
    const float* Wv   = (const float*)d_in[3];
    const float* posw = (const float*)d_in[4];
    const float* posb = (const float*)d_in[5];
    const float* gq   = (const float*)d_in[6];
    const float* bq   = (const float*)d_in[7];
    const float* mq   = (const float*)d_in[8];
    const float* vq   = (const float*)d_in[9];
    const float* gv   = (const float*)d_in[10];
    const float* bv   = (const float*)d_in[11];
    const float* mv   = (const float*)d_in[12];
    const float* vv   = (const float*)d_in[13];
    float* out = (float*)d_out;

    cudaFuncSetAttribute(lambda_main3,
                         cudaFuncAttributeMaxDynamicSharedMemorySize, LSM_TOTAL);

    zero_lc_kernel<<<16, 1024>>>();
    proj_kernel<<<dim3(25, 6, 16), 256>>>(x, Wq, Wk, Wv,
                                          gq, bq, mq, vq, gv, bv, mv, vv);
    softmax_kernel<<<BB * 64, 256>>>();
    lc_kernel<<<dim3(16, 56), 256>>>();
    lambda_main3<<<dim3(56, 16), 256, LSM_TOTAL>>>(posw, posb, out);
}

// round 7
// speedup vs baseline: 1.4539x; 1.0288x over previous
#include <cuda_runtime.h>
#include <cuda_bf16.h>

// ---------------- problem constants ----------------
#define BB     16
#define CCH    256
#define HH     56
#define WWID   56
#define NN     3136          // 56*56
#define NHEADS 4
#define DK     16
#define DU     4
#define DVV    64
#define RR     15
// conv pad = 7

typedef unsigned long long ull;

// ---------------- scratch (device globals; no allocations allowed) ----------------
__device__ float g_q[BB * 64 * NN];    // [b][h*16+k][n]   (BN applied)
__device__ float g_k[BB * 64 * NN];    // [b][u*16+k][n]   (softmaxed in place)
__device__ float g_v[BB * 256 * NN];   // [b][u*64+v][n]   (BN applied)
__device__ float g_Lc[BB * DK * DVV];  // [b][k][v]

// ---------------- f32x2 helpers (sm_103a packed fp32 pipe) ----------------
__device__ __forceinline__ void ffma2(ull &d, ull a, ull b) {
    asm volatile("fma.rn.f32x2 %0, %1, %2, %0;" : "+l"(d) : "l"(a), "l"(b));
}
__device__ __forceinline__ ull pack2(float x) {
    ull r; asm("mov.b64 %0, {%1, %1};" : "=l"(r) : "f"(x)); return r;
}
__device__ __forceinline__ ull fpack(float lo, float hi) {
    ull r; asm("mov.b64 %0, {%1, %2};" : "=l"(r) : "f"(lo), "f"(hi)); return r;
}
__device__ __forceinline__ void funpack(ull v, float &lo, float &hi) {
    asm("mov.b64 {%0, %1}, %2;" : "=f"(lo), "=f"(hi) : "l"(v));
}

// ---------------- kernel 0: zero Lc accumulator ----------------
__global__ void zero_lc_kernel() {
    int i = blockIdx.x * blockDim.x + threadIdx.x;
    if (i < BB * DK * DVV) g_Lc[i] = 0.f;
}

// ---------------- kernel 1: fused 1x1-conv projections + BatchNorm ----------------
__global__ void __launch_bounds__(256) proj_kernel(
    const float* __restrict__ x,
    const float* __restrict__ Wq, const float* __restrict__ Wk, const float* __restrict__ Wv,
    const float* __restrict__ gq, const float* __restrict__ bq,
    const float* __restrict__ mq, const float* __restrict__ vq,
    const float* __restrict__ gv, const float* __restrict__ bv,
    const float* __restrict__ mv, const float* __restrict__ vv)
{
    __shared__ float xs[32 * 128];
    __shared__ float Ws[32 * 64];

    const int b  = blockIdx.z;
    const int db = blockIdx.y;
    const int n0 = blockIdx.x * 128;
    const int t  = threadIdx.x;
    const int tx = t & 15;
    const int ty = t >> 4;

    const float* Wsrc; int dstride, dcol0;
    if (db == 0)      { Wsrc = Wq; dstride = 64;  dcol0 = 0; }
    else if (db == 1) { Wsrc = Wk; dstride = 64;  dcol0 = 0; }
    else              { Wsrc = Wv; dstride = 256; dcol0 = (db - 2) * 64; }

    ull acc[16];
#pragma unroll
    for (int i = 0; i < 16; i++) acc[i] = 0ull;

    for (int c0 = 0; c0 < CCH; c0 += 32) {
        __syncthreads();
        for (int s = t; s < 32 * 128; s += 256) {
            int cc = s >> 7, nn = s & 127;
            int g = n0 + nn;
            xs[s] = (g < NN) ? x[(size_t)(b * CCH + c0 + cc) * NN + g] : 0.f;
        }
        for (int s = t; s < 32 * 64; s += 256) {
            int cc = s >> 6, dd = s & 63;
            Ws[s] = Wsrc[(size_t)(c0 + cc) * dstride + dcol0 + dd];
        }
        __syncthreads();

#pragma unroll 8
        for (int ccl = 0; ccl < 32; ccl++) {
            ull xv[4];
#pragma unroll
            for (int j = 0; j < 4; j++)
                xv[j] = *(const ull*)&xs[ccl * 128 + ((tx + 16 * j) << 1)];
#pragma unroll
            for (int i = 0; i < 4; i++) {
                ull w2 = pack2(Ws[ccl * 64 + ty * 4 + i]);
#pragma unroll
                for (int j = 0; j < 4; j++) ffma2(acc[i * 4 + j], xv[j], w2);
            }
        }
    }

    float* dst;
    if (db == 0)      dst = g_q + (size_t)b * 64 * NN;
    else if (db == 1) dst = g_k + (size_t)b * 64 * NN;
    else              dst = g_v + ((size_t)b * 256 + dcol0) * NN;

    float sc[4], sh[4];
#pragma unroll
    for (int i = 0; i < 4; i++) {
        int d = ty * 4 + i;
        if (db == 0) {
            float inv = gq[d] * rsqrtf(vq[d] + 1e-5f);
            sc[i] = inv; sh[i] = bq[d] - mq[d] * inv;
        } else if (db == 1) {
            sc[i] = 1.f; sh[i] = 0.f;
        } else {
            int uvi = dcol0 + d;
            float inv = gv[uvi] * rsqrtf(vv[uvi] + 1e-5f);
            sc[i] = inv; sh[i] = bv[uvi] - mv[uvi] * inv;
        }
    }
#pragma unroll
    for (int i = 0; i < 4; i++) {
#pragma unroll
        for (int j = 0; j < 4; j++) {
            int n = n0 + ((tx + 16 * j) << 1);
            if (n < NN) {
                float lo, hi; funpack(acc[i * 4 + j], lo, hi);
                float* p = dst + (size_t)(ty * 4 + i) * NN + n;
                p[0] = lo * sc[i] + sh[i];
                p[1] = hi * sc[i] + sh[i];
            }
        }
    }
}

// ---------------- kernel 2: softmax over positions, in place on g_k ----------------
__global__ void __launch_bounds__(256) softmax_kernel() {
    const int row = blockIdx.x;
    float* base = g_k + (size_t)row * NN;
    const int t = threadIdx.x;
    __shared__ float red[8];

    float m = -3e38f;
    for (int i = t; i < NN; i += 256) m = fmaxf(m, base[i]);
#pragma unroll
    for (int o = 16; o; o >>= 1) m = fmaxf(m, __shfl_xor_sync(0xffffffffu, m, o));
    if ((t & 31) == 0) red[t >> 5] = m;
    __syncthreads();
    float mx = red[0];
#pragma unroll
    for (int w = 1; w < 8; w++) mx = fmaxf(mx, red[w]);
    __syncthreads();

    float s = 0.f;
    for (int i = t; i < NN; i += 256) {
        float e = expf(base[i] - mx);
        base[i] = e;
        s += e;
    }
#pragma unroll
    for (int o = 16; o; o >>= 1) s += __shfl_xor_sync(0xffffffffu, s, o);
    if ((t & 31) == 0) red[t >> 5] = s;
    __syncthreads();
    float S = 0.f;
#pragma unroll
    for (int w = 0; w < 8; w++) S += red[w];
    float inv = 1.f / S;
    for (int i = t; i < NN; i += 256) base[i] *= inv;
}

// ---------------- kernel 3: Lc[b,k,v] ----------------
__global__ void __launch_bounds__(256) lc_kernel() {
    const int b  = blockIdx.x;
    const int sp = blockIdx.y;
    __shared__ float ks[56 * 17];
    __shared__ float vs[56 * 65];
    const int t  = threadIdx.x;
    const int vc = t & 63;
    const int kg = t >> 6;

    const int m0 = sp * 56;
    float acc[4] = {0.f, 0.f, 0.f, 0.f};
    for (int u = 0; u < 4; u++) {
        __syncthreads();
        for (int s = t; s < 16 * 56; s += 256) {
            int kc = s / 56, m = s % 56;
            ks[m * 17 + kc] = g_k[(size_t)((b * 4 + u) * 16 + kc) * NN + m0 + m];
        }
        for (int s = t; s < 64 * 56; s += 256) {
            int c = s / 56, m = s % 56;
            vs[m * 65 + c] = g_v[(size_t)((b * 4 + u) * 64 + c) * NN + m0 + m];
        }
        __syncthreads();
        for (int m = 0; m < 56; m++) {
            float vvv = vs[m * 65 + vc];
#pragma unroll
            for (int i = 0; i < 4; i++) acc[i] += ks[m * 17 + kg * 4 + i] * vvv;
        }
    }
#pragma unroll
    for (int i = 0; i < 4; i++)
        atomicAdd(&g_Lc[((size_t)b * 16 + kg * 4 + i) * DVV + vc], acc[i]);
}

// ---------------- kernel 4: lambda, software-pipelined (1 barrier / dy) ----------
// Same algebra as R6 (qw = q*w first; 28.9 GF). Changes:
//  - double-buffered vrow AND qwd; region = {stage vrow(dy+1); phase1(dy+1);
//    phase2(dy)} with ONE __syncthreads per dy -> stalls overlap across phases.
//  - phase1: k-outer with 8 independent dx accumulators (no serial RAW chain);
//    q read directly from global (L1-hot: row reused 54x within launch).
//  - qs dropped from smem to fit 2 CTAs/SM at 109.2 kB.
// Dynamic smem layout (float offsets):
//   qwd  ull[2][15][56][4] @ 0       (13440 floats)   16B-aligned (first)
//   wsu  [16][225]         @ 13440   (3600)
//   vrow [2][70][66]       @ 17040   (9240)  zero-padded halo, alternating
//   lcp  [16][64]          @ 26280   (1024)
#define LSM_WSU   13440
#define LSM_VROW  17040
#define LSM_LCP   26280
#define LSM_TOTAL (27304 * 4)

__global__ void __launch_bounds__(256, 2) lambda_main4(
    const float* __restrict__ posw, const float* __restrict__ posb,
    float* __restrict__ out)
{
    extern __shared__ float sm[];
    ull*   qwd  = (ull*)sm;            // [2][3360]
    float* wsu  = sm + LSM_WSU;
    float* vrow = sm + LSM_VROW;       // [2][4620]
    float* lcp  = sm + LSM_LCP;

    const int y    = blockIdx.x;
    const int b    = blockIdx.y;
    const int t    = threadIdx.x;
    const int w    = t >> 5;
    const int lane = t & 31;
    // phase-1 role: warp -> (h, dx half)
    const int ph   = w >> 1;
    const int pd0  = (w & 1) ? 8 : 0;
    const int pdn  = (w & 1) ? 7 : 8;

    // prolog: Lc'+pos_b, zero both vrow buffers (halo pads stay 0 forever)
    for (int s = t; s < 1024; s += 256)
        lcp[s] = g_Lc[(size_t)b * 1024 + s] + posb[s >> 6];
    for (int s = t; s < 2 * 4620; s += 256) vrow[s] = 0.f;

    ull acc[4][7];
#pragma unroll
    for (int h = 0; h < 4; h++)
#pragma unroll
        for (int xi = 0; xi < 7; xi++) acc[h][xi] = 0ull;

    const int dylo = (y < 7) ? 7 - y : 0;
    const int dyhi = (y > 48) ? 62 - y : 14;
    int buf = 0;

    // ---- helper lambdas (inlined) ----
    auto stage_vrow = [&](float* vrb, int u, int row) {
        const float* vsrc = g_v + ((size_t)((b * 4 + u) * 64)) * NN + row * 56;
        for (int s = t; s < 64 * 14; s += 256) {
            int v = s / 14, x4 = s % 14;
            float4 v4 = *(const float4*)(vsrc + (size_t)v * NN + x4 * 4);
            float* d = vrb + (x4 * 4 + 7) * 66 + v;
            d[0] = v4.x; d[66] = v4.y; d[132] = v4.z; d[198] = v4.w;
        }
    };
    auto phase1 = [&](ull* qb, int dy) {
        if (lane >= 28) return;
        ull a[8];
#pragma unroll
        for (int j = 0; j < 8; j++) a[j] = 0ull;
        const float* qg = g_q + (size_t)(b * 64 + ph * 16) * NN + y * 56 + 2 * lane;
        const float* wr = wsu + dy * 15 + pd0;
#pragma unroll
        for (int k = 0; k < 16; k++) {
            ull qk = *(const ull*)(qg + (size_t)k * NN);
            const float* wk = wr + k * 225;
#pragma unroll
            for (int j = 0; j < 8; j++)        // j=7 for odd warps reads 1 float
                ffma2(a[j], qk, pack2(wk[j])); // past wsu (inside smem, discarded)
        }
#pragma unroll
        for (int j = 0; j < 8; j++) {
            if (j < pdn) {
                float lo, hi; funpack(a[j], lo, hi);
                ull* dst = qb + (size_t)(((pd0 + j) * 56 + 2 * lane) * 4 + ph);
                dst[0] = fpack(lo, lo);
                dst[4] = fpack(hi, hi);
            }
        }
    };
    auto phase2 = [&](const float* vrb, const ull* qb) {
        const ull* vbase = (const ull*)vrb + 7 * w * 33 + lane;
        {
            ull vwin[14];
#pragma unroll
            for (int i = 0; i < 14; i++) vwin[i] = vbase[i * 33];
#pragma unroll
            for (int dx = 0; dx < 8; dx++) {
                const ulonglong2* qq = (const ulonglong2*)qb + (dx * 56 + 7 * w) * 2;
#pragma unroll
                for (int xi = 0; xi < 7; xi++) {
                    ulonglong2 q01 = qq[2 * xi];
                    ulonglong2 q23 = qq[2 * xi + 1];
                    ull a = vwin[xi + dx];
                    ffma2(acc[0][xi], a, q01.x);
                    ffma2(acc[1][xi], a, q01.y);
                    ffma2(acc[2][xi], a, q23.x);
                    ffma2(acc[3][xi], a, q23.y);
                }
            }
        }
        {
            ull vwin[13];
#pragma unroll
            for (int i = 0; i < 13; i++) vwin[i] = vbase[(8 + i) * 33];
#pragma unroll
            for (int dx2 = 0; dx2 < 7; dx2++) {
                const int dx = 8 + dx2;
                const ulonglong2* qq = (const ulonglong2*)qb + (dx * 56 + 7 * w) * 2;
#pragma unroll
                for (int xi = 0; xi < 7; xi++) {
                    ulonglong2 q01 = qq[2 * xi];
                    ulonglong2 q23 = qq[2 * xi + 1];
                    ull a = vwin[xi + dx2];
                    ffma2(acc[0][xi], a, q01.x);
                    ffma2(acc[1][xi], a, q01.y);
                    ffma2(acc[2][xi], a, q23.x);
                    ffma2(acc[3][xi], a, q23.y);
                }
            }
        }
    };

    // ---- pipelined main loops ----
    for (int u = 0; u < 4; u++) {
        __syncthreads();                      // prior phase1/phase2 done
        for (int s = t; s < 3600; s += 256)   // wsu[k][tap]
            wsu[s] = posw[(size_t)(s / 225) * 900 + u * 225 + (s % 225)];
        __syncthreads();                      // wsu visible

        // pipeline fill: first dy of this u
        stage_vrow(vrow + buf * 4620, u, y + dylo - 7);
        phase1(qwd + buf * 3360, dylo);

        for (int dy = dylo; dy <= dyhi; dy++) {
            __syncthreads();                  // buf data ready; buf^1 free
            if (dy < dyhi) {
                stage_vrow(vrow + (buf ^ 1) * 4620, u, y + dy + 1 - 7);
                phase1(qwd + (buf ^ 1) * 3360, dy + 1);
            }
            phase2(vrow + buf * 4620, qwd + buf * 3360);
            buf ^= 1;
        }
    }

    // ---- epilogue: Y = acc + sum_k q[h,k,n]*(Lc[k,v]+pos_b[k]) ----
    __syncthreads();
    float* ybuf = vrow;   // reuse (9240 floats >= 64*56)
    ull L[16];
#pragma unroll
    for (int k = 0; k < 16; k++) L[k] = *(const ull*)(lcp + k * 64 + 2 * lane);

    const int xbase = 7 * w;
    for (int h = 0; h < 4; h++) {
#pragma unroll
        for (int xi = 0; xi < 7; xi++) {
            ull yv = acc[h][xi];
            const float* qc = g_q + (size_t)(b * 64 + h * 16) * NN + y * 56 + xbase + xi;
#pragma unroll
            for (int k = 0; k < 16; k++) ffma2(yv, pack2(qc[(size_t)k * NN]), L[k]);
            float lo, hi; funpack(yv, lo, hi);
            ybuf[(2 * lane)     * 56 + xbase + xi] = lo;
            ybuf[(2 * lane + 1) * 56 + xbase + xi] = hi;
        }
        __syncthreads();
        float* obase = out + ((size_t)(b * 256 + h * 64)) * NN + y * 56;
        for (int s = t; s < 64 * 14; s += 256) {
            int v = s / 14, x4 = s % 14;
            const float* sb = ybuf + v * 56 + x4 * 4;
            float4 v4; v4.x = sb[0]; v4.y = sb[1]; v4.z = sb[2]; v4.w = sb[3];
            *(float4*)(obase + (size_t)v * NN + x4 * 4) = v4;
        }
        __syncthreads();
    }
}

// ---------------- launch ----------------
extern "C" void kernel_launch(void* const* d_in, const int* in_sizes, int n_in,
                              void* d_out, int out_size) {
    const float* x    = (const float*)d_in[0];
    const float* Wq   = (const float*)d_in[1];
    const float* Wk   = (const float*)d_in[2];
    const float* Wv   = (const float*)d_in[3];
    const float* posw = (const float*)d_in[4];
    const float* posb = (const float*)d_in[5];
    const float* gq   = (const float*)d_in[6];
    const float* bq   = (const float*)d_in[7];
    const float* mq   = (const float*)d_in[8];
    const float* vq   = (const float*)d_in[9];
    const float* gv   = (const float*)d_in[10];
    const float* bv   = (const float*)d_in[11];
    const float* mv   = (const float*)d_in[12];
    const float* vv   = (const float*)d_in[13];
    float* out = (float*)d_out;

    cudaFuncSetAttribute(lambda_main4,
                         cudaFuncAttributeMaxDynamicSharedMemorySize, LSM_TOTAL);

    zero_lc_kernel<<<16, 1024>>>();
    proj_kernel<<<dim3(25, 6, 16), 256>>>(x, Wq, Wk, Wv,
                                          gq, bq, mq, vq, gv, bv, mv, vv);
    softmax_kernel<<<BB * 64, 256>>>();
    lc_kernel<<<dim3(16, 56), 256>>>();
    lambda_main4<<<dim3(56, 16), 256, LSM_TOTAL>>>(posw, posb, out);
}